// round 4
// baseline (speedup 1.0000x reference)
#include <cuda_runtime.h>
#include <cuda_bf16.h>
#include <mma.h>
#include <math.h>

using namespace nvcuda;

// ---------------- problem constants ----------------
#define NL 2          // layers
#define NB 4          // batch
#define NT 64         // time
#define ND 512        // input dim
#define NH 512        // hidden/proj dim
#define NC 4096       // cell dim
#define NG (4*NC)     // 16384 gate rows per dir
#define CLIPV 3.0f

// ---------------- device scratch (static allocation: allowed) ----------------
__device__ __align__(16) float g_pi[(size_t)2 * NB * NT * NG];   // [dir][b][t][g]  32 MiB
__device__ __align__(16) float g_x [(size_t)2 * NB * NT * NH];   // layer input  [dir][b][t][i]
__device__ __align__(16) float g_y [(size_t)2 * NB * NT * NH];   // layer raw out [dir][b][t][i]
__device__ __align__(16) float g_s [(size_t)2 * NB * NC];        // sigma(o)*tanh(c_new)
__device__ __align__(16) float g_c [(size_t)2 * NB * NC];        // cell state
__device__ __align__(16) float g_h [(size_t)2 * NB * NH];        // hidden state

__device__ __forceinline__ float dot4(float4 a, float4 b) {
    return a.x*b.x + a.y*b.y + a.z*b.z + a.w*b.w;
}
__device__ __forceinline__ float sigmoidf_(float x) { return 1.0f / (1.0f + expf(-x)); }
__device__ __forceinline__ float clip3(float x)     { return fminf(CLIPV, fmaxf(-CLIPV, x)); }

// ---------------- init: zero h and c (per layer! reference resets state each
// _run_direction call, i.e. every layer and direction) ----------------
__global__ void init_state_kernel() {
    int idx = blockIdx.x * blockDim.x + threadIdx.x;
    if (idx < 2 * NB * NC) g_c[idx] = 0.0f;
    if (idx < 2 * NB * NH) g_h[idx] = 0.0f;
}

// ---------------- pi GEMM: pi[d][m][n] = A[m,:] . Wi[n,:]  (split-bf16, 3 MMAs) ----
// A: (256,512) row-major fp32 (inputs for l==0, g_x[dir] for l==1)
// grid: x = N/64 = 256 tiles, y = M/128 = 2 tiles, z = dir
__global__ void __launch_bounds__(256)
pi_kernel(const float* __restrict__ x0, const float* __restrict__ Wi_l, int l)
{
    const int d = blockIdx.z;
    const float* A  = l ? (g_x + (size_t)d * (NB * NT * NH)) : x0;
    const float* Bg = Wi_l + (size_t)d * NG * ND;
    const int mBase = blockIdx.y * 128;
    const int nBase = blockIdx.x * 64;

    __shared__ __nv_bfloat16 As[2][128][40];  // [hi/lo][m][k], ld=40 (16B multiple)
    __shared__ __nv_bfloat16 Bs[2][64][40];   // [hi/lo][n][k]

    wmma::fragment<wmma::accumulator, 16, 16, 16, float> acc[2][2];
#pragma unroll
    for (int i = 0; i < 2; i++)
#pragma unroll
        for (int j = 0; j < 2; j++) wmma::fill_fragment(acc[i][j], 0.0f);

    const int w  = threadIdx.x >> 5;
    const int wm = w >> 1;      // 0..3 -> 32-row M slab
    const int wn = w & 1;       // 0..1 -> 32-col N slab

    for (int kk = 0; kk < 16; kk++) {
        const int k0 = kk * 32;
        // stage A tile 128x32 fp32 -> hi/lo bf16
#pragma unroll
        for (int rpt = 0; rpt < 4; rpt++) {
            int id = threadIdx.x + rpt * 256;   // 0..1023
            int r = id >> 3, c = (id & 7) << 2;
            float4 v = *(const float4*)(A + (size_t)(mBase + r) * ND + k0 + c);
            float vs[4] = {v.x, v.y, v.z, v.w};
#pragma unroll
            for (int q = 0; q < 4; q++) {
                __nv_bfloat16 hi = __float2bfloat16(vs[q]);
                As[0][r][c + q] = hi;
                As[1][r][c + q] = __float2bfloat16(vs[q] - __bfloat162float(hi));
            }
        }
        // stage B tile 64x32
#pragma unroll
        for (int rpt = 0; rpt < 2; rpt++) {
            int id = threadIdx.x + rpt * 256;   // 0..511
            int r = id >> 3, c = (id & 7) << 2;
            float4 v = *(const float4*)(Bg + (size_t)(nBase + r) * ND + k0 + c);
            float vs[4] = {v.x, v.y, v.z, v.w};
#pragma unroll
            for (int q = 0; q < 4; q++) {
                __nv_bfloat16 hi = __float2bfloat16(vs[q]);
                Bs[0][r][c + q] = hi;
                Bs[1][r][c + q] = __float2bfloat16(vs[q] - __bfloat162float(hi));
            }
        }
        __syncthreads();

#pragma unroll
        for (int ks = 0; ks < 2; ks++) {
            wmma::fragment<wmma::matrix_a, 16, 16, 16, __nv_bfloat16, wmma::row_major> ah[2], al[2];
            wmma::fragment<wmma::matrix_b, 16, 16, 16, __nv_bfloat16, wmma::col_major> bh[2], bl[2];
#pragma unroll
            for (int i = 0; i < 2; i++) {
                wmma::load_matrix_sync(ah[i], &As[0][wm * 32 + i * 16][ks * 16], 40);
                wmma::load_matrix_sync(al[i], &As[1][wm * 32 + i * 16][ks * 16], 40);
            }
#pragma unroll
            for (int j = 0; j < 2; j++) {
                wmma::load_matrix_sync(bh[j], &Bs[0][wn * 32 + j * 16][ks * 16], 40);
                wmma::load_matrix_sync(bl[j], &Bs[1][wn * 32 + j * 16][ks * 16], 40);
            }
#pragma unroll
            for (int i = 0; i < 2; i++)
#pragma unroll
                for (int j = 0; j < 2; j++) {
                    wmma::mma_sync(acc[i][j], ah[i], bh[j], acc[i][j]);
                    wmma::mma_sync(acc[i][j], ah[i], bl[j], acc[i][j]);
                    wmma::mma_sync(acc[i][j], al[i], bh[j], acc[i][j]);
                }
        }
        __syncthreads();
    }

#pragma unroll
    for (int i = 0; i < 2; i++)
#pragma unroll
        for (int j = 0; j < 2; j++) {
            float* cp = g_pi + ((size_t)d * (NB * NT) + mBase + wm * 32 + i * 16) * NG
                             + nBase + wn * 32 + j * 16;
            wmma::store_matrix_sync(cp, acc[i][j], NG, wmma::mem_row_major);
        }
}

// ---------------- step 1: gates + cell update + s = sig(o)*tanh(c_new) ---------
// grid: 1024 blocks x 256 threads. block -> (dir, 8 cells). warp -> one cell j,
// computes 4 gate dots x 4 batches against smem-resident h.
__global__ void __launch_bounds__(256)
step_gates_kernel(const float* __restrict__ Ws_l,   // (2, 16384, 512) for this layer
                  const float* __restrict__ bs_l,   // (2, 16384)
                  const int*   __restrict__ mask, int t)
{
    __shared__ float sh[NB * NH];   // h for this dir: 8 KB
    const int d  = blockIdx.x >> 9;
    const int cb = (blockIdx.x & 511) * 8;
    const int td = d ? (NT - 1 - t) : t;
    const int tid = threadIdx.x;

    const float* hsrc = g_h + (size_t)d * NB * NH;
    for (int i = tid; i < NB * NH; i += 256) sh[i] = hsrc[i];
    __syncthreads();

    const int w = tid >> 5, lane = tid & 31;
    const int j = cb + w;
    const float* wbase = Ws_l + (size_t)d * NG * ND;

    float acc[4][4];
#pragma unroll
    for (int q = 0; q < 4; q++)
#pragma unroll
        for (int b = 0; b < 4; b++) acc[q][b] = 0.0f;

#pragma unroll
    for (int it = 0; it < 4; it++) {
        const int k = it * 128 + lane * 4;
        float4 hv0 = *(const float4*)&sh[0 * NH + k];
        float4 hv1 = *(const float4*)&sh[1 * NH + k];
        float4 hv2 = *(const float4*)&sh[2 * NH + k];
        float4 hv3 = *(const float4*)&sh[3 * NH + k];
#pragma unroll
        for (int q = 0; q < 4; q++) {
            float4 wv = *(const float4*)&wbase[(size_t)(q * NC + j) * ND + k];
            acc[q][0] += dot4(wv, hv0);
            acc[q][1] += dot4(wv, hv1);
            acc[q][2] += dot4(wv, hv2);
            acc[q][3] += dot4(wv, hv3);
        }
    }
#pragma unroll
    for (int off = 16; off > 0; off >>= 1)
#pragma unroll
        for (int q = 0; q < 4; q++)
#pragma unroll
            for (int b = 0; b < 4; b++)
                acc[q][b] += __shfl_xor_sync(0xffffffffu, acc[q][b], off);

    if (lane < 4) {
        const int b = lane;
        const float* pib = g_pi + (((size_t)d * NB + b) * NT + td) * NG;
        const float* bsd = bs_l + (size_t)d * NG;
        float gi = acc[0][b] + pib[0 * NC + j] + bsd[0 * NC + j];
        float gf = acc[1][b] + pib[1 * NC + j] + bsd[1 * NC + j];
        float gg = acc[2][b] + pib[2 * NC + j] + bsd[2 * NC + j];
        float go = acc[3][b] + pib[3 * NC + j] + bsd[3 * NC + j];

        const size_t ci = ((size_t)d * NB + b) * NC + j;
        float cold = g_c[ci];
        float cn = clip3(sigmoidf_(gi) * tanhf(gg) + sigmoidf_(gf) * cold);
        if (mask[b * NT + td] != 0) g_c[ci] = cn;
        g_s[ci] = sigmoidf_(go) * tanhf(cn);
    }
}

// ---------------- step 2: h_new = clip(s @ Wp^T); update h; emit y -------------
// grid: 128 blocks x 256 threads. warp -> one output index i (all 4 batches).
__global__ void __launch_bounds__(256)
step_proj_kernel(const float* __restrict__ Wp_l,    // (2, 512, 4096) for this layer
                 const int*   __restrict__ mask, int t)
{
    const int d  = blockIdx.x >> 6;
    const int ib = (blockIdx.x & 63) * 8;
    const int td = d ? (NT - 1 - t) : t;
    const int w = threadIdx.x >> 5, lane = threadIdx.x & 31;
    const int iOut = ib + w;

    const float* wrow = Wp_l + ((size_t)d * NH + iOut) * NC;
    const float* sbase = g_s + (size_t)d * NB * NC;

    float acc[4] = {0.f, 0.f, 0.f, 0.f};
#pragma unroll
    for (int it = 0; it < 32; it++) {
        const int k = it * 128 + lane * 4;
        float4 wv = *(const float4*)&wrow[k];
        float4 s0 = *(const float4*)&sbase[0 * NC + k];
        float4 s1 = *(const float4*)&sbase[1 * NC + k];
        float4 s2 = *(const float4*)&sbase[2 * NC + k];
        float4 s3 = *(const float4*)&sbase[3 * NC + k];
        acc[0] += dot4(wv, s0);
        acc[1] += dot4(wv, s1);
        acc[2] += dot4(wv, s2);
        acc[3] += dot4(wv, s3);
    }
#pragma unroll
    for (int off = 16; off > 0; off >>= 1)
#pragma unroll
        for (int b = 0; b < 4; b++)
            acc[b] += __shfl_xor_sync(0xffffffffu, acc[b], off);

    if (lane < 4) {
        const int b = lane;
        float v = clip3(acc[b]);
        const size_t yi = (((size_t)d * NB + b) * NT + td) * NH + iOut;
        if (mask[b * NT + td] != 0) {
            g_h[((size_t)d * NB + b) * NH + iOut] = v;
            g_y[yi] = v;
        } else {
            g_y[yi] = 0.0f;
        }
    }
}

// ---------------- finalize layer: skip-add, write output, feed next layer ------
__global__ void __launch_bounds__(512)
finalize_kernel(float* __restrict__ out, int l)
{
    const int idx = blockIdx.x * blockDim.x + threadIdx.x;   // 0 .. 262143
    const int i  = idx & (NH - 1);
    const int tt = (idx >> 9) & (NT - 1);
    const int b  = (idx >> 15) & (NB - 1);
    const int d  = idx >> 17;
    float z = g_y[idx] + (l ? g_x[idx] : 0.0f);
    g_x[idx] = z;
    out[(((size_t)l * NB + b) * NT + tt) * (2 * NH) + d * NH + i] = z;
}

// ---------------- launcher ----------------
extern "C" void kernel_launch(void* const* d_in, const int* in_sizes, int n_in,
                              void* d_out, int out_size)
{
    const float* inputs = (const float*)d_in[0];   // (4,64,512)
    const int*   mask   = (const int*)  d_in[1];   // (4,64)
    const float* Wi     = (const float*)d_in[2];   // (2,2,16384,512)
    const float* Ws     = (const float*)d_in[3];   // (2,2,16384,512)
    const float* bs     = (const float*)d_in[4];   // (2,2,16384)
    const float* Wp     = (const float*)d_in[5];   // (2,2,512,4096)
    float* out = (float*)d_out;                    // (2,4,64,1024)

    for (int l = 0; l < NL; l++) {
        const float* Wi_l = Wi + (size_t)l * 2 * NG * ND;
        const float* Ws_l = Ws + (size_t)l * 2 * NG * ND;
        const float* bs_l = bs + (size_t)l * 2 * NG;
        const float* Wp_l = Wp + (size_t)l * 2 * NH * NC;

        // Reference zeroes (h0, c0) for EVERY layer/direction — reset here.
        init_state_kernel<<<144, 256>>>();

        dim3 gp(NG / 64, (NB * NT) / 128, 2);
        pi_kernel<<<gp, 256>>>(inputs, Wi_l, l);

        for (int t = 0; t < NT; t++) {
            step_gates_kernel<<<1024, 256>>>(Ws_l, bs_l, mask, t);
            step_proj_kernel<<<128, 256>>>(Wp_l, mask, t);
        }
        finalize_kernel<<<512, 512>>>(out, l);
    }
}

// round 5
// speedup vs baseline: 1.2414x; 1.2414x over previous
#include <cuda_runtime.h>
#include <cuda_bf16.h>
#include <mma.h>
#include <math.h>

using namespace nvcuda;

// ---------------- problem constants ----------------
#define NL 2          // layers
#define NB 4          // batch
#define NT 64         // time
#define ND 512        // input dim
#define NH 512        // hidden/proj dim
#define NC 4096       // cell dim
#define NG (4*NC)     // 16384 gate rows per dir
#define CLIPV 3.0f

// ---------------- device scratch (static allocation: allowed) ----------------
__device__ __align__(16) float g_pi[(size_t)2 * NB * NT * NG];   // [dir][b][t][g]  32 MiB
__device__ __align__(16) float g_x [(size_t)2 * NB * NT * NH];   // layer input  [dir][b][t][i]
__device__ __align__(16) float g_y [(size_t)2 * NB * NT * NH];   // layer raw out [dir][b][t][i]
__device__ __align__(16) float g_s [(size_t)2 * NB * NC];        // sigma(o)*tanh(c_new)
__device__ __align__(16) float g_c [(size_t)2 * NB * NC];        // cell state
__device__ __align__(16) float g_h [(size_t)2 * NB * NH];        // hidden state
// proj k-split partials: idx = ((d*NH + i)*NB + b)*8 + kc
__device__ __align__(16) float g_pp[(size_t)2 * NH * NB * 8];
__device__ int g_cnt[2 * 64];   // arrival counters per (d, i-group); zero-init, self-resetting

__device__ __forceinline__ float dot4(float4 a, float4 b) {
    return a.x*b.x + a.y*b.y + a.z*b.z + a.w*b.w;
}
__device__ __forceinline__ float sigmoidf_(float x) { return 1.0f / (1.0f + expf(-x)); }
__device__ __forceinline__ float clip3(float x)     { return fminf(CLIPV, fmaxf(-CLIPV, x)); }

// ---------------- init: zero h and c (reference resets per layer/direction) ----
__global__ void init_state_kernel() {
    int idx = blockIdx.x * blockDim.x + threadIdx.x;
    if (idx < 2 * NB * NC) g_c[idx] = 0.0f;
    if (idx < 2 * NB * NH) g_h[idx] = 0.0f;
}

// ---------------- pi GEMM: pi[d][m][n] = A[m,:] . Wi[n,:]  (split-bf16, 3 MMAs) ----
__global__ void __launch_bounds__(256)
pi_kernel(const float* __restrict__ x0, const float* __restrict__ Wi_l, int l)
{
    const int d = blockIdx.z;
    const float* A  = l ? (g_x + (size_t)d * (NB * NT * NH)) : x0;
    const float* Bg = Wi_l + (size_t)d * NG * ND;
    const int mBase = blockIdx.y * 128;
    const int nBase = blockIdx.x * 64;

    __shared__ __nv_bfloat16 As[2][128][40];  // [hi/lo][m][k], ld=40
    __shared__ __nv_bfloat16 Bs[2][64][40];   // [hi/lo][n][k]

    wmma::fragment<wmma::accumulator, 16, 16, 16, float> acc[2][2];
#pragma unroll
    for (int i = 0; i < 2; i++)
#pragma unroll
        for (int j = 0; j < 2; j++) wmma::fill_fragment(acc[i][j], 0.0f);

    const int w  = threadIdx.x >> 5;
    const int wm = w >> 1;
    const int wn = w & 1;

    for (int kk = 0; kk < 16; kk++) {
        const int k0 = kk * 32;
#pragma unroll
        for (int rpt = 0; rpt < 4; rpt++) {
            int id = threadIdx.x + rpt * 256;
            int r = id >> 3, c = (id & 7) << 2;
            float4 v = *(const float4*)(A + (size_t)(mBase + r) * ND + k0 + c);
            float vs[4] = {v.x, v.y, v.z, v.w};
#pragma unroll
            for (int q = 0; q < 4; q++) {
                __nv_bfloat16 hi = __float2bfloat16(vs[q]);
                As[0][r][c + q] = hi;
                As[1][r][c + q] = __float2bfloat16(vs[q] - __bfloat162float(hi));
            }
        }
#pragma unroll
        for (int rpt = 0; rpt < 2; rpt++) {
            int id = threadIdx.x + rpt * 256;
            int r = id >> 3, c = (id & 7) << 2;
            float4 v = *(const float4*)(Bg + (size_t)(nBase + r) * ND + k0 + c);
            float vs[4] = {v.x, v.y, v.z, v.w};
#pragma unroll
            for (int q = 0; q < 4; q++) {
                __nv_bfloat16 hi = __float2bfloat16(vs[q]);
                Bs[0][r][c + q] = hi;
                Bs[1][r][c + q] = __float2bfloat16(vs[q] - __bfloat162float(hi));
            }
        }
        __syncthreads();

#pragma unroll
        for (int ks = 0; ks < 2; ks++) {
            wmma::fragment<wmma::matrix_a, 16, 16, 16, __nv_bfloat16, wmma::row_major> ah[2], al[2];
            wmma::fragment<wmma::matrix_b, 16, 16, 16, __nv_bfloat16, wmma::col_major> bh[2], bl[2];
#pragma unroll
            for (int i = 0; i < 2; i++) {
                wmma::load_matrix_sync(ah[i], &As[0][wm * 32 + i * 16][ks * 16], 40);
                wmma::load_matrix_sync(al[i], &As[1][wm * 32 + i * 16][ks * 16], 40);
            }
#pragma unroll
            for (int j = 0; j < 2; j++) {
                wmma::load_matrix_sync(bh[j], &Bs[0][wn * 32 + j * 16][ks * 16], 40);
                wmma::load_matrix_sync(bl[j], &Bs[1][wn * 32 + j * 16][ks * 16], 40);
            }
#pragma unroll
            for (int i = 0; i < 2; i++)
#pragma unroll
                for (int j = 0; j < 2; j++) {
                    wmma::mma_sync(acc[i][j], ah[i], bh[j], acc[i][j]);
                    wmma::mma_sync(acc[i][j], ah[i], bl[j], acc[i][j]);
                    wmma::mma_sync(acc[i][j], al[i], bh[j], acc[i][j]);
                }
        }
        __syncthreads();
    }

#pragma unroll
    for (int i = 0; i < 2; i++)
#pragma unroll
        for (int j = 0; j < 2; j++) {
            float* cp = g_pi + ((size_t)d * (NB * NT) + mBase + wm * 32 + i * 16) * NG
                             + nBase + wn * 32 + j * 16;
            wmma::store_matrix_sync(cp, acc[i][j], NG, wmma::mem_row_major);
        }
}

// ---------------- step 1: gates + cell update + s = sig(o)*tanh(c_new) ---------
__global__ void __launch_bounds__(256)
step_gates_kernel(const float* __restrict__ Ws_l,   // (2, 16384, 512)
                  const float* __restrict__ bs_l,   // (2, 16384)
                  const int*   __restrict__ mask, int t)
{
    __shared__ float sh[NB * NH];
    const int d  = blockIdx.x >> 9;
    const int cb = (blockIdx.x & 511) * 8;
    const int td = d ? (NT - 1 - t) : t;
    const int tid = threadIdx.x;

    const float* hsrc = g_h + (size_t)d * NB * NH;
    for (int i = tid; i < NB * NH; i += 256) sh[i] = hsrc[i];
    __syncthreads();

    const int w = tid >> 5, lane = tid & 31;
    const int j = cb + w;
    const float* wbase = Ws_l + (size_t)d * NG * ND;

    float acc[4][4];
#pragma unroll
    for (int q = 0; q < 4; q++)
#pragma unroll
        for (int b = 0; b < 4; b++) acc[q][b] = 0.0f;

#pragma unroll
    for (int it = 0; it < 4; it++) {
        const int k = it * 128 + lane * 4;
        float4 hv0 = *(const float4*)&sh[0 * NH + k];
        float4 hv1 = *(const float4*)&sh[1 * NH + k];
        float4 hv2 = *(const float4*)&sh[2 * NH + k];
        float4 hv3 = *(const float4*)&sh[3 * NH + k];
#pragma unroll
        for (int q = 0; q < 4; q++) {
            float4 wv = *(const float4*)&wbase[(size_t)(q * NC + j) * ND + k];
            acc[q][0] += dot4(wv, hv0);
            acc[q][1] += dot4(wv, hv1);
            acc[q][2] += dot4(wv, hv2);
            acc[q][3] += dot4(wv, hv3);
        }
    }
#pragma unroll
    for (int off = 16; off > 0; off >>= 1)
#pragma unroll
        for (int q = 0; q < 4; q++)
#pragma unroll
            for (int b = 0; b < 4; b++)
                acc[q][b] += __shfl_xor_sync(0xffffffffu, acc[q][b], off);

    if (lane < 4) {
        const int b = lane;
        const float* pib = g_pi + (((size_t)d * NB + b) * NT + td) * NG;
        const float* bsd = bs_l + (size_t)d * NG;
        // __ldcs: pi is read exactly once — evict-first so the 32 MB pi stream
        // doesn't push the L2-resident Ws/Wp (84 MB) out of the 126 MB L2.
        float gi = acc[0][b] + __ldcs(&pib[0 * NC + j]) + bsd[0 * NC + j];
        float gf = acc[1][b] + __ldcs(&pib[1 * NC + j]) + bsd[1 * NC + j];
        float gg = acc[2][b] + __ldcs(&pib[2 * NC + j]) + bsd[2 * NC + j];
        float go = acc[3][b] + __ldcs(&pib[3 * NC + j]) + bsd[3 * NC + j];

        const size_t ci = ((size_t)d * NB + b) * NC + j;
        float cold = g_c[ci];
        float cn = clip3(sigmoidf_(gi) * tanhf(gg) + sigmoidf_(gf) * cold);
        if (mask[b * NT + td] != 0) g_c[ci] = cn;
        g_s[ci] = sigmoidf_(go) * tanhf(cn);
    }
}

// ---------------- step 2: h_new = clip(s @ Wp^T)  (K-split, last-block reduce) --
// grid: 1024 blocks = 2 d x 64 i-groups x 8 k-chunks; 256 threads (8 warps).
// warp w -> output i = ig*8 + w over a 512-wide K chunk, all 4 batches.
// Partials land in g_pp; the last-arriving block per (d, ig) reduces 8 chunks
// in fixed index order (deterministic), applies clip+mask, writes h and y,
// and resets its counter for the next launch / graph replay.
__global__ void __launch_bounds__(256)
step_proj_kernel(const float* __restrict__ Wp_l,    // (2, 512, 4096)
                 const int*   __restrict__ mask, int t)
{
    const int d  = blockIdx.x >> 9;
    const int ig = (blockIdx.x >> 3) & 63;
    const int kc = blockIdx.x & 7;
    const int td = d ? (NT - 1 - t) : t;

    __shared__ float ss[NB * 512];   // s chunk for this (d, kc): 8 KB
    const float* sbase = g_s + (size_t)d * NB * NC + kc * 512;
    for (int idx = threadIdx.x; idx < NB * 512; idx += 256) {
        int b = idx >> 9, k = idx & 511;
        ss[idx] = sbase[(size_t)b * NC + k];
    }
    __syncthreads();

    const int w = threadIdx.x >> 5, lane = threadIdx.x & 31;
    const int iOut = ig * 8 + w;
    const float* wrow = Wp_l + ((size_t)d * NH + iOut) * NC + kc * 512;

    float acc[4] = {0.f, 0.f, 0.f, 0.f};
#pragma unroll
    for (int it = 0; it < 4; it++) {
        const int k = it * 128 + lane * 4;
        float4 wv = *(const float4*)&wrow[k];
        acc[0] += dot4(wv, *(const float4*)&ss[0 * 512 + k]);
        acc[1] += dot4(wv, *(const float4*)&ss[1 * 512 + k]);
        acc[2] += dot4(wv, *(const float4*)&ss[2 * 512 + k]);
        acc[3] += dot4(wv, *(const float4*)&ss[3 * 512 + k]);
    }
#pragma unroll
    for (int off = 16; off > 0; off >>= 1)
#pragma unroll
        for (int b = 0; b < 4; b++)
            acc[b] += __shfl_xor_sync(0xffffffffu, acc[b], off);

    if (lane < 4)
        g_pp[(((size_t)d * NH + iOut) * NB + lane) * 8 + kc] = acc[lane];

    // signal completion of this chunk-block
    __threadfence();
    __syncthreads();
    __shared__ int isLast;
    if (threadIdx.x == 0)
        isLast = (atomicAdd(&g_cnt[d * 64 + ig], 1) == 7);
    __syncthreads();
    if (!isLast) return;

    // last block: reduce 8 partials for 8 outputs x 4 batches (32 lanes)
    if (threadIdx.x < 32) {
        const int wi = threadIdx.x >> 2;       // 0..7
        const int b  = threadIdx.x & 3;
        const int io = ig * 8 + wi;
        const float* pp = &g_pp[(((size_t)d * NH + io) * NB + b) * 8];
        float v = 0.0f;
#pragma unroll
        for (int c = 0; c < 8; c++) v += __ldcg(&pp[c]);   // L2 reads, fixed order
        v = clip3(v);
        const size_t yi = (((size_t)d * NB + b) * NT + td) * NH + io;
        if (mask[b * NT + td] != 0) {
            g_h[((size_t)d * NB + b) * NH + io] = v;
            g_y[yi] = v;
        } else {
            g_y[yi] = 0.0f;
        }
    }
    if (threadIdx.x == 0) g_cnt[d * 64 + ig] = 0;   // reset for next launch
}

// ---------------- finalize layer: skip-add, write output, feed next layer ------
__global__ void __launch_bounds__(512)
finalize_kernel(float* __restrict__ out, int l)
{
    const int idx = blockIdx.x * blockDim.x + threadIdx.x;   // 0 .. 262143
    const int i  = idx & (NH - 1);
    const int tt = (idx >> 9) & (NT - 1);
    const int b  = (idx >> 15) & (NB - 1);
    const int d  = idx >> 17;
    float z = g_y[idx] + (l ? g_x[idx] : 0.0f);
    g_x[idx] = z;
    out[(((size_t)l * NB + b) * NT + tt) * (2 * NH) + d * NH + i] = z;
}

// ---------------- launcher ----------------
extern "C" void kernel_launch(void* const* d_in, const int* in_sizes, int n_in,
                              void* d_out, int out_size)
{
    const float* inputs = (const float*)d_in[0];   // (4,64,512)
    const int*   mask   = (const int*)  d_in[1];   // (4,64)
    const float* Wi     = (const float*)d_in[2];   // (2,2,16384,512)
    const float* Ws     = (const float*)d_in[3];   // (2,2,16384,512)
    const float* bs     = (const float*)d_in[4];   // (2,2,16384)
    const float* Wp     = (const float*)d_in[5];   // (2,2,512,4096)
    float* out = (float*)d_out;                    // (2,4,64,1024)

    for (int l = 0; l < NL; l++) {
        const float* Wi_l = Wi + (size_t)l * 2 * NG * ND;
        const float* Ws_l = Ws + (size_t)l * 2 * NG * ND;
        const float* bs_l = bs + (size_t)l * 2 * NG;
        const float* Wp_l = Wp + (size_t)l * 2 * NH * NC;

        init_state_kernel<<<144, 256>>>();   // per-layer state reset (reference semantics)

        dim3 gp(NG / 64, (NB * NT) / 128, 2);
        pi_kernel<<<gp, 256>>>(inputs, Wi_l, l);

        for (int t = 0; t < NT; t++) {
            step_gates_kernel<<<1024, 256>>>(Ws_l, bs_l, mask, t);
            step_proj_kernel<<<1024, 256>>>(Wp_l, mask, t);
        }
        finalize_kernel<<<512, 512>>>(out, l);
    }
}